// round 15
// baseline (speedup 1.0000x reference)
#include <cuda_runtime.h>
#include <cuda_bf16.h>
#include <cstdint>
#include <cstddef>

// ---------------------------------------------------------------------------
// RetinaNet head as implicit GEMM (NHWC bf16, mma.sync m16n8k16, fp32 accum)
//
//   For each level l (shared weights across levels):
//     X0 = NHWC bf16 of f_l
//     cls tower: 4x [GEMM(2304->256) + bias + relu]   (K = 9 taps * 256 cin)
//     cls final: GEMM(2304->720) + bias, scattered into out[:, :, 0:80]
//     box tower / box final: same with 36 channels -> out[:, :, 80:84]
// ---------------------------------------------------------------------------

#define DEVFN __device__ __forceinline__

static const int RTOT = 120087;

// ---------------- static device scratch (no allocations allowed) -----------
__device__ __align__(128) __nv_bfloat16 g_X   [2 * 10000 * 256];
__device__ __align__(128) __nv_bfloat16 g_bufA[2 * 10000 * 256];
__device__ __align__(128) __nv_bfloat16 g_bufB[2 * 10000 * 256];
// 8 tower convs (2304x256) + cls_score (2304x768 padded) + box_pred (2304x128 padded)
__device__ __align__(128) __nv_bfloat16 g_wt[8 * 2304 * 256 + 2304 * 768 + 2304 * 128];

// ---------------- PTX helpers ----------------------------------------------
DEVFN uint32_t smem_u32(const void* p) {
    return (uint32_t)__cvta_generic_to_shared(p);
}
DEVFN void cp_async16(uint32_t dst, const void* src, int sz) {
    asm volatile("cp.async.cg.shared.global [%0], [%1], 16, %2;\n"
                 :: "r"(dst), "l"(src), "r"(sz));
}
DEVFN void cp_commit() { asm volatile("cp.async.commit_group;\n" ::: "memory"); }
template <int N> DEVFN void cp_wait() {
    asm volatile("cp.async.wait_group %0;\n" :: "n"(N) : "memory");
}
DEVFN void ldmat_x4(uint32_t* r, uint32_t addr) {
    asm volatile("ldmatrix.sync.aligned.m8n8.x4.shared.b16 {%0,%1,%2,%3}, [%4];\n"
                 : "=r"(r[0]), "=r"(r[1]), "=r"(r[2]), "=r"(r[3]) : "r"(addr));
}
DEVFN void ldmat_x4_t(uint32_t* r, uint32_t addr) {
    asm volatile("ldmatrix.sync.aligned.m8n8.x4.trans.shared.b16 {%0,%1,%2,%3}, [%4];\n"
                 : "=r"(r[0]), "=r"(r[1]), "=r"(r[2]), "=r"(r[3]) : "r"(addr));
}
DEVFN void mma16816(float* d, const uint32_t* a, const uint32_t* b) {
    asm volatile(
        "mma.sync.aligned.m16n8k16.row.col.f32.bf16.bf16.f32 "
        "{%0,%1,%2,%3},{%4,%5,%6,%7},{%8,%9},{%0,%1,%2,%3};\n"
        : "+f"(d[0]), "+f"(d[1]), "+f"(d[2]), "+f"(d[3])
        : "r"(a[0]), "r"(a[1]), "r"(a[2]), "r"(a[3]), "r"(b[0]), "r"(b[1]));
}

// ---------------- weight transform: (O,C,3,3) f32 -> [t*256+c][o] bf16 ------
__global__ void wt_kernel(const float* __restrict__ w, __nv_bfloat16* __restrict__ dst,
                          int O, int OP) {
    int idx = blockIdx.x * 256 + threadIdx.x;
    if (idx >= 2304 * OP) return;
    int row = idx / OP, o = idx - row * OP;
    int t = row >> 8;        // tap 0..8
    int c = row & 255;       // cin
    float v = (o < O) ? w[(o * 256 + c) * 9 + t] : 0.f;
    dst[idx] = __float2bfloat16(v);
}

// ---------------- input convert: NCHW f32 -> NHWC bf16 ----------------------
__global__ void conv_in_kernel(const float* __restrict__ f, __nv_bfloat16* __restrict__ X,
                               int HW) {
    int idx = blockIdx.x * 256 + threadIdx.x;
    if (idx >= 2 * HW * 256) return;
    int m = idx >> 8, c = idx & 255;
    int n = (m >= HW);
    int p = m - n * HW;
    X[idx] = __float2bfloat16(f[(n * 256 + c) * HW + p]);
}

// ---------------- the implicit-GEMM conv kernel -----------------------------
// BM=128 (spatial rows), BN=128 (out channels), BK=32, 72 k-iters (9 taps x 8)
// 8 warps: 2 (M) x 4 (N), warp tile 64x32, mma m16n8k16, 3-stage cp.async.
// mode 0: tower (bias+relu -> NHWC bf16)
// mode 1: cls final (bias -> out[(n*RTOT+Roff+p*9+a)*84 + k], o=a*80+k, o<720)
// mode 2: box final (bias -> out[...*84 + 80 + j],           o=a*4+j,  o<36)
__global__ __launch_bounds__(256, 2)
void gemm_conv(const __nv_bfloat16* __restrict__ X,
               const __nv_bfloat16* __restrict__ Wt,
               const float* __restrict__ bias,
               __nv_bfloat16* __restrict__ Yb,
               float* __restrict__ Yf,
               int H, int W, int HW, int Mtot, int OP,
               int mode, int Ovalid, int Roff) {
    __shared__ __align__(16) __nv_bfloat16 sA[3][128 * 32];
    __shared__ __align__(16) __nv_bfloat16 sB[3][32 * 128];

    const int tid  = threadIdx.x;
    const int lane = tid & 31, wid = tid >> 5;
    const int wm = wid & 1, wn = wid >> 1;
    const int mBase = blockIdx.x * 128;
    const int nBase = blockIdx.y * 128;

    // --- per-thread A-load bookkeeping: 2 rows x 1 chunk(16B) ---
    const int ar = tid >> 2;   // 0..63
    const int ac = tid & 3;    // k-chunk within BK (8 bf16 each)
    int rowm[2], rx[2], ry[2];
    bool rin[2];
#pragma unroll
    for (int i = 0; i < 2; i++) {
        int m = mBase + ar + i * 64;
        rowm[i] = m;
        bool inb = m < Mtot;
        int mm = inb ? m : 0;
        int n = (mm >= HW);
        int p = mm - n * HW;
        ry[i] = p / W;
        rx[i] = p - ry[i] * W;
        rin[i] = inb;
    }
    // --- per-thread B-load bookkeeping: 1 row x 2 granules(16B) ---
    const int bk  = tid >> 3;  // 0..31
    const int bg0 = tid & 7;

    float acc[4][4][4];
#pragma unroll
    for (int a = 0; a < 4; a++)
#pragma unroll
        for (int b = 0; b < 4; b++)
#pragma unroll
            for (int c = 0; c < 4; c++) acc[a][b][c] = 0.f;

    auto load_tiles = [&](int kt, int st) {
        int tap = kt >> 3, cc = kt & 7;
        int dy = tap / 3 - 1, dx = (tap % 3) - 1;
        // A tile: 128 rows x 32 k (swizzled chunk = (chunk + row) & 3)
#pragma unroll
        for (int i = 0; i < 2; i++) {
            int r = ar + i * 64;
            bool v = rin[i] && (unsigned)(ry[i] + dy) < (unsigned)H &&
                     (unsigned)(rx[i] + dx) < (unsigned)W;
            size_t gidx = v ? ((size_t)(rowm[i] + dy * W + dx) * 256 + cc * 32 + ac * 8)
                            : (size_t)0;
            uint32_t dst = smem_u32(&sA[st][r * 32 + (((ac + r) & 3) << 3)]);
            cp_async16(dst, X + gidx, v ? 16 : 0);
        }
        // B tile: 32 k-rows x 128 cols (swizzled granule = g ^ (k & 7))
        const __nv_bfloat16* wrow = Wt + (size_t)(kt * 32 + bk) * OP + nBase;
#pragma unroll
        for (int i = 0; i < 2; i++) {
            int g = bg0 + i * 8;
            uint32_t dst = smem_u32(&sB[st][bk * 128 + ((g ^ (bk & 7)) << 3)]);
            cp_async16(dst, wrow + g * 8, 16);
        }
        cp_commit();
    };

    load_tiles(0, 0);
    load_tiles(1, 1);

#pragma unroll 1
    for (int kt = 0; kt < 72; kt++) {
        int st = kt % 3;
        cp_wait<1>();
        __syncthreads();
        if (kt + 2 < 72) load_tiles(kt + 2, (kt + 2) % 3);
        else             cp_commit();   // keep group counting aligned

#pragma unroll
        for (int ks = 0; ks < 2; ks++) {
            uint32_t afr[4][4], bfr[2][4];
#pragma unroll
            for (int mi = 0; mi < 4; mi++) {
                int row = wm * 64 + mi * 16 + (lane & 15);
                int ch  = ks * 2 + (lane >> 4);
                ldmat_x4(afr[mi],
                         smem_u32(&sA[st][row * 32 + (((ch + row) & 3) << 3)]));
            }
#pragma unroll
            for (int pr = 0; pr < 2; pr++) {
                int k = ks * 16 + ((lane >> 3) & 1) * 8 + (lane & 7);
                int g = wn * 4 + pr * 2 + (lane >> 4);
                ldmat_x4_t(bfr[pr],
                           smem_u32(&sB[st][k * 128 + ((g ^ (k & 7)) << 3)]));
            }
#pragma unroll
            for (int mi = 0; mi < 4; mi++)
#pragma unroll
                for (int ni = 0; ni < 4; ni++)
                    mma16816(acc[mi][ni], afr[mi], &bfr[ni >> 1][(ni & 1) * 2]);
        }
    }

    // ------------------------------ epilogue ------------------------------
    const int g4 = lane >> 2;  // accumulator row within 8
    const int q  = lane & 3;   // accumulator col pair
#pragma unroll
    for (int mi = 0; mi < 4; mi++) {
#pragma unroll
        for (int half = 0; half < 2; half++) {
            int m = mBase + wm * 64 + mi * 16 + g4 + half * 8;
            if (m >= Mtot) continue;
            if (mode == 0) {
#pragma unroll
                for (int ni = 0; ni < 4; ni++) {
                    int col = nBase + wn * 32 + ni * 8 + q * 2;
                    float v0 = fmaxf(acc[mi][ni][half * 2 + 0] + bias[col], 0.f);
                    float v1 = fmaxf(acc[mi][ni][half * 2 + 1] + bias[col + 1], 0.f);
                    *reinterpret_cast<__nv_bfloat162*>(Yb + (size_t)m * 256 + col) =
                        __floats2bfloat162_rn(v0, v1);
                }
            } else {
                int n = (m >= HW);
                int p = m - n * HW;
                size_t rowbase = (size_t)n * RTOT + Roff + (size_t)p * 9;
#pragma unroll
                for (int ni = 0; ni < 4; ni++) {
                    int col = nBase + wn * 32 + ni * 8 + q * 2;
#pragma unroll
                    for (int e = 0; e < 2; e++) {
                        int o = col + e;
                        if (o < Ovalid) {
                            float v = acc[mi][ni][half * 2 + e] + bias[o];
                            if (mode == 1) {
                                int a = o / 80, kk = o - a * 80;
                                Yf[(rowbase + a) * 84 + kk] = v;
                            } else {
                                int a = o >> 2, j = o & 3;
                                Yf[(rowbase + a) * 84 + 80 + j] = v;
                            }
                        }
                    }
                }
            }
        }
    }
}

// ---------------- host launcher ---------------------------------------------
extern "C" void kernel_launch(void* const* d_in, const int* in_sizes, int n_in,
                              void* d_out, int out_size) {
    (void)in_sizes; (void)n_in; (void)out_size;

    const float* f[5];
    for (int i = 0; i < 5; i++) f[i] = (const float*)d_in[i];
    const float *tw[8], *tb[8];
    for (int i = 0; i < 4; i++) { tw[i]     = (const float*)d_in[5  + 2 * i];
                                  tb[i]     = (const float*)d_in[6  + 2 * i]; }
    for (int i = 0; i < 4; i++) { tw[4 + i] = (const float*)d_in[13 + 2 * i];
                                  tb[4 + i] = (const float*)d_in[14 + 2 * i]; }
    const float* csw = (const float*)d_in[21];
    const float* csb = (const float*)d_in[22];
    const float* bpw = (const float*)d_in[23];
    const float* bpb = (const float*)d_in[24];
    float* out = (float*)d_out;

    __nv_bfloat16 *X, *BA, *BB, *WT;
    cudaGetSymbolAddress((void**)&X,  g_X);
    cudaGetSymbolAddress((void**)&BA, g_bufA);
    cudaGetSymbolAddress((void**)&BB, g_bufB);
    cudaGetSymbolAddress((void**)&WT, g_wt);

    const size_t TS = (size_t)2304 * 256;
    __nv_bfloat16* wtC = WT + 8 * TS;
    __nv_bfloat16* wtB = wtC + (size_t)2304 * 768;

    // weight transforms (cheap, graph-capturable)
    for (int i = 0; i < 8; i++)
        wt_kernel<<<(2304 * 256) / 256, 256>>>(tw[i], WT + i * TS, 256, 256);
    wt_kernel<<<(2304 * 768) / 256, 256>>>(csw, wtC, 720, 768);
    wt_kernel<<<(2304 * 128) / 256, 256>>>(bpw, wtB, 36, 128);

    static const int LH[5]    = {100, 50, 25, 13, 7};
    static const int LROFF[5] = {0, 90000, 112500, 118125, 119646};

    for (int l = 0; l < 5; l++) {
        int H = LH[l], W = LH[l], HW = H * W;
        int Mtot = 2 * HW;
        int Mt = (Mtot + 127) / 128;

        conv_in_kernel<<<Mtot, 256>>>(f[l], X, HW);  // Mtot*256/256 = Mtot blocks

        __nv_bfloat16* pp[2] = {BA, BB};

        // cls tower + cls final
        const __nv_bfloat16* src = X;
        for (int i = 0; i < 4; i++) {
            gemm_conv<<<dim3(Mt, 2), 256>>>(src, WT + i * TS, tb[i], pp[i & 1], nullptr,
                                            H, W, HW, Mtot, 256, 0, 256, 0);
            src = pp[i & 1];
        }
        gemm_conv<<<dim3(Mt, 6), 256>>>(src, wtC, csb, nullptr, out,
                                        H, W, HW, Mtot, 768, 1, 720, LROFF[l]);

        // box tower + box final
        src = X;
        for (int i = 0; i < 4; i++) {
            gemm_conv<<<dim3(Mt, 2), 256>>>(src, WT + (4 + i) * TS, tb[4 + i], pp[i & 1],
                                            nullptr, H, W, HW, Mtot, 256, 0, 256, 0);
            src = pp[i & 1];
        }
        gemm_conv<<<dim3(Mt, 1), 256>>>(src, wtB, bpb, nullptr, out,
                                        H, W, HW, Mtot, 128, 2, 36, LROFF[l]);
    }
}

// round 16
// speedup vs baseline: 3.0269x; 3.0269x over previous
#include <cuda_runtime.h>
#include <cuda_bf16.h>
#include <cstdint>
#include <cstddef>

// ---------------------------------------------------------------------------
// RetinaNet head, all 5 FPN levels batched into ONE unified M dimension.
// Weights shared across levels => each conv layer = one implicit GEMM:
//   M = 2*(10000+2500+625+169+49) = 26686 rows (NHWC bf16), K = 9*256 = 2304.
// 7 launches total: wt_all, conv_in_all, 4x fused (cls+box) tower layers,
// 1 fused finals launch (6 cls n-tiles + 1 box n-tile) scattering straight
// into the permuted (N, 120087, 84) fp32 output.
// ---------------------------------------------------------------------------

#define DEVFN __device__ __forceinline__

constexpr int    RTOT = 120087;
constexpr int    NM   = 26686;              // total rows across levels & batch
constexpr int    MT   = (NM + 127) / 128;   // 209 M-tiles
constexpr size_t HOFF = (size_t)NM * 256;   // cls/box half offset in buffers

__constant__ int c_Moff[5] = {0, 20000, 25000, 26250, 26588};
__constant__ int c_HW[5]   = {10000, 2500, 625, 169, 49};
__constant__ int c_Wl[5]   = {100, 50, 25, 13, 7};
__constant__ int c_Roff[5] = {0, 90000, 112500, 118125, 119646};

DEVFN int level_of(int m) {
    return (m >= 20000) + (m >= 25000) + (m >= 26250) + (m >= 26588);
}

// ---------------- static device scratch (no allocations allowed) -----------
__device__ __align__(128) __nv_bfloat16 g_X   [(size_t)NM * 256];
__device__ __align__(128) __nv_bfloat16 g_bufA[2 * (size_t)NM * 256];
__device__ __align__(128) __nv_bfloat16 g_bufB[2 * (size_t)NM * 256];
// 8 tower convs (2304x256) + cls_score (2304x768 padded) + box_pred (2304x128)
__device__ __align__(128) __nv_bfloat16 g_wt[8 * 2304 * 256 + 2304 * 768 + 2304 * 128];

// ---------------- PTX helpers ----------------------------------------------
DEVFN uint32_t smem_u32(const void* p) {
    return (uint32_t)__cvta_generic_to_shared(p);
}
DEVFN void cp_async16(uint32_t dst, const void* src, int sz) {
    asm volatile("cp.async.cg.shared.global [%0], [%1], 16, %2;\n"
                 :: "r"(dst), "l"(src), "r"(sz));
}
DEVFN void cp_commit() { asm volatile("cp.async.commit_group;\n" ::: "memory"); }
template <int N> DEVFN void cp_wait() {
    asm volatile("cp.async.wait_group %0;\n" :: "n"(N) : "memory");
}
DEVFN void ldmat_x4(uint32_t* r, uint32_t addr) {
    asm volatile("ldmatrix.sync.aligned.m8n8.x4.shared.b16 {%0,%1,%2,%3}, [%4];\n"
                 : "=r"(r[0]), "=r"(r[1]), "=r"(r[2]), "=r"(r[3]) : "r"(addr));
}
DEVFN void ldmat_x4_t(uint32_t* r, uint32_t addr) {
    asm volatile("ldmatrix.sync.aligned.m8n8.x4.trans.shared.b16 {%0,%1,%2,%3}, [%4];\n"
                 : "=r"(r[0]), "=r"(r[1]), "=r"(r[2]), "=r"(r[3]) : "r"(addr));
}
DEVFN void mma16816(float* d, const uint32_t* a, const uint32_t* b) {
    asm volatile(
        "mma.sync.aligned.m16n8k16.row.col.f32.bf16.bf16.f32 "
        "{%0,%1,%2,%3},{%4,%5,%6,%7},{%8,%9},{%0,%1,%2,%3};\n"
        : "+f"(d[0]), "+f"(d[1]), "+f"(d[2]), "+f"(d[3])
        : "r"(a[0]), "r"(a[1]), "r"(a[2]), "r"(a[3]), "r"(b[0]), "r"(b[1]));
}

// ---------------- fused weight transform (one launch, all 10 convs) ---------
// (O,C,3,3) f32 -> [tap*256 + c][o] bf16, O padded to OP with zeros.
struct Ptrs10 { const float* p[10]; };

__global__ void wt_all(Ptrs10 Wsrc, __nv_bfloat16* __restrict__ dst) {
    int idx = blockIdx.x * 256 + threadIdx.x;
    const int TS    = 2304 * 256;
    const int C_END = 8 * TS + 2304 * 768;
    int which, base, OP, O;
    if (idx < 8 * TS)      { which = idx / TS; base = which * TS; OP = 256; O = 256; }
    else if (idx < C_END)  { which = 8; base = 8 * TS; OP = 768; O = 720; }
    else                   { which = 9; base = C_END;  OP = 128; O = 36; }
    int rel = idx - base;
    int row = rel / OP;
    int o   = rel - row * OP;
    int t = row >> 8, c = row & 255;
    float v = (o < O) ? Wsrc.p[which][((size_t)o * 256 + c) * 9 + t] : 0.f;
    dst[idx] = __float2bfloat16(v);
}

// ---------------- fused input convert: all levels NCHW f32 -> NHWC bf16 -----
struct Ptrs5 { const float* p[5]; };

__global__ void conv_in_all(Ptrs5 F, __nv_bfloat16* __restrict__ X) {
    int idx = blockIdx.x * 256 + threadIdx.x;   // exactly NM*256 threads
    int m = idx >> 8, c = idx & 255;
    int lvl = level_of(m);
    int rel = m - c_Moff[lvl];
    int HW  = c_HW[lvl];
    int n   = rel >= HW;
    int p   = rel - n * HW;
    X[idx] = __float2bfloat16(F.p[lvl][((size_t)n * 256 + c) * HW + p]);
}

// ---------------- the implicit-GEMM conv kernel -----------------------------
// BM=128 (unified spatial rows), BN=128, BK=32, 72 k-iters (9 taps x 8 chunks)
// 8 warps 2(M)x4(N), warp tile 64x32, mma m16n8k16, 3-stage cp.async.
// KIND 0: tower layer, blockIdx.z selects cls/box  (bias+relu -> bf16 NHWC)
// KIND 1: finals, blockIdx.y<6 = cls (OP=768, valid 720), ==6 = box (OP=128,
//         valid 36); scatter into out[(n*RTOT + Roff + p*9 + a)*84 + ...]
struct GArgs {
    const __nv_bfloat16* srcA;   // cls input
    const __nv_bfloat16* srcB;   // box input
    const __nv_bfloat16* wA;
    const __nv_bfloat16* wB;
    const float* biasA;
    const float* biasB;
    __nv_bfloat16* dstA;
    __nv_bfloat16* dstB;
    float* out;
};

template <int KIND>
__global__ __launch_bounds__(256, 2)
void gemm_conv(GArgs g) {
    __shared__ __align__(16) __nv_bfloat16 sA[3][128 * 32];
    __shared__ __align__(16) __nv_bfloat16 sB[3][32 * 128];

    const int tid  = threadIdx.x;
    const int lane = tid & 31, wid = tid >> 5;
    const int wm = wid & 1, wn = wid >> 1;
    const int mBase = blockIdx.x * 128;

    const __nv_bfloat16 *X, *Wt;
    const float* bias;
    __nv_bfloat16* Yb = nullptr;
    int OP, nBase, Ovalid = 0;
    bool clsmode = true;
    if (KIND == 0) {
        bool box = (blockIdx.z != 0);
        X    = box ? g.srcB  : g.srcA;
        Wt   = box ? g.wB    : g.wA;
        bias = box ? g.biasB : g.biasA;
        Yb   = box ? g.dstB  : g.dstA;
        OP = 256; nBase = blockIdx.y * 128;
    } else {
        clsmode = (blockIdx.y < 6);
        X    = clsmode ? g.srcA  : g.srcB;
        Wt   = clsmode ? g.wA    : g.wB;
        bias = clsmode ? g.biasA : g.biasB;
        OP     = clsmode ? 768 : 128;
        nBase  = clsmode ? (int)blockIdx.y * 128 : 0;
        Ovalid = clsmode ? 720 : 36;
    }

    // --- per-thread A-load bookkeeping: 2 rows x 1 chunk(16B), level decode ---
    const int ar = tid >> 2;   // 0..63
    const int ac = tid & 3;    // k-chunk within BK (8 bf16 each)
    int rowm[2], rx[2], ry[2], wd[2];
    bool rin[2];
#pragma unroll
    for (int i = 0; i < 2; i++) {
        int m = mBase + ar + i * 64;
        rowm[i] = m;
        bool inb = (m < NM);
        int mm = inb ? m : 0;
        int lvl = level_of(mm);
        int rel = mm - c_Moff[lvl];
        int HW  = c_HW[lvl];
        int Wd  = c_Wl[lvl];
        int n   = rel >= HW;
        int p   = rel - n * HW;
        ry[i] = p / Wd;
        rx[i] = p - ry[i] * Wd;
        wd[i] = Wd;
        rin[i] = inb;
    }
    // --- per-thread B-load bookkeeping: 1 row x 2 granules(16B) ---
    const int bk  = tid >> 3;  // 0..31
    const int bg0 = tid & 7;

    float acc[4][4][4];
#pragma unroll
    for (int a = 0; a < 4; a++)
#pragma unroll
        for (int b = 0; b < 4; b++)
#pragma unroll
            for (int c = 0; c < 4; c++) acc[a][b][c] = 0.f;

    auto load_tiles = [&](int kt, int st) {
        int tap = kt >> 3, cc = kt & 7;
        int dy = tap / 3 - 1, dx = (tap % 3) - 1;
        // A tile: conflict-free swizzle chunk' = ac ^ ((row>>1)&3)
#pragma unroll
        for (int i = 0; i < 2; i++) {
            int r = ar + i * 64;
            bool v = rin[i] && (unsigned)(ry[i] + dy) < (unsigned)wd[i] &&
                     (unsigned)(rx[i] + dx) < (unsigned)wd[i];
            size_t gidx = v ? ((size_t)(rowm[i] + dy * wd[i] + dx) * 256 + cc * 32 + ac * 8)
                            : (size_t)0;
            uint32_t dst = smem_u32(&sA[st][r * 32 + ((ac ^ ((r >> 1) & 3)) << 3)]);
            cp_async16(dst, X + gidx, v ? 16 : 0);
        }
        // B tile: 32 k-rows x 128 cols (granule g ^ (k & 7))
        const __nv_bfloat16* wrow = Wt + (size_t)(kt * 32 + bk) * OP + nBase;
#pragma unroll
        for (int i = 0; i < 2; i++) {
            int gg = bg0 + i * 8;
            uint32_t dst = smem_u32(&sB[st][bk * 128 + ((gg ^ (bk & 7)) << 3)]);
            cp_async16(dst, wrow + gg * 8, 16);
        }
        cp_commit();
    };

    load_tiles(0, 0);
    load_tiles(1, 1);

#pragma unroll 1
    for (int kt = 0; kt < 72; kt++) {
        int st = kt % 3;
        cp_wait<1>();
        __syncthreads();
        if (kt + 2 < 72) load_tiles(kt + 2, (kt + 2) % 3);
        else             cp_commit();   // keep group counting aligned

#pragma unroll
        for (int ks = 0; ks < 2; ks++) {
            uint32_t afr[4][4], bfr[2][4];
#pragma unroll
            for (int mi = 0; mi < 4; mi++) {
                int row = wm * 64 + mi * 16 + (lane & 15);
                int ch  = ks * 2 + (lane >> 4);
                ldmat_x4(afr[mi],
                         smem_u32(&sA[st][row * 32 + ((ch ^ ((row >> 1) & 3)) << 3)]));
            }
#pragma unroll
            for (int pr = 0; pr < 2; pr++) {
                int k = ks * 16 + ((lane >> 3) & 1) * 8 + (lane & 7);
                int gg = wn * 4 + pr * 2 + (lane >> 4);
                ldmat_x4_t(bfr[pr],
                           smem_u32(&sB[st][k * 128 + ((gg ^ (k & 7)) << 3)]));
            }
#pragma unroll
            for (int mi = 0; mi < 4; mi++)
#pragma unroll
                for (int ni = 0; ni < 4; ni++)
                    mma16816(acc[mi][ni], afr[mi], &bfr[ni >> 1][(ni & 1) * 2]);
        }
    }

    // ------------------------------ epilogue ------------------------------
    const int g4 = lane >> 2;  // accumulator row within 8
    const int q  = lane & 3;   // accumulator col pair
#pragma unroll
    for (int mi = 0; mi < 4; mi++) {
#pragma unroll
        for (int half = 0; half < 2; half++) {
            int m = mBase + wm * 64 + mi * 16 + g4 + half * 8;
            if (m >= NM) continue;
            if (KIND == 0) {
#pragma unroll
                for (int ni = 0; ni < 4; ni++) {
                    int col = nBase + wn * 32 + ni * 8 + q * 2;
                    float v0 = fmaxf(acc[mi][ni][half * 2 + 0] + bias[col], 0.f);
                    float v1 = fmaxf(acc[mi][ni][half * 2 + 1] + bias[col + 1], 0.f);
                    *reinterpret_cast<__nv_bfloat162*>(Yb + (size_t)m * 256 + col) =
                        __floats2bfloat162_rn(v0, v1);
                }
            } else {
                int lvl = level_of(m);
                int rel = m - c_Moff[lvl];
                int HW  = c_HW[lvl];
                int n   = rel >= HW;
                int p   = rel - n * HW;
                size_t rowbase = (size_t)n * RTOT + c_Roff[lvl] + (size_t)p * 9;
#pragma unroll
                for (int ni = 0; ni < 4; ni++) {
                    int col = nBase + wn * 32 + ni * 8 + q * 2;
#pragma unroll
                    for (int e = 0; e < 2; e++) {
                        int o = col + e;
                        if (o < Ovalid) {
                            float v = acc[mi][ni][half * 2 + e] + bias[o];
                            if (clsmode) {
                                int a = o / 80, kk = o - a * 80;
                                g.out[(rowbase + a) * 84 + kk] = v;
                            } else {
                                int a = o >> 2, j = o & 3;
                                g.out[(rowbase + a) * 84 + 80 + j] = v;
                            }
                        }
                    }
                }
            }
        }
    }
}

// ---------------- host launcher ---------------------------------------------
extern "C" void kernel_launch(void* const* d_in, const int* in_sizes, int n_in,
                              void* d_out, int out_size) {
    (void)in_sizes; (void)n_in; (void)out_size;

    const float* f[5];
    for (int i = 0; i < 5; i++) f[i] = (const float*)d_in[i];
    const float *tw[8], *tb[8];
    for (int i = 0; i < 4; i++) { tw[i]     = (const float*)d_in[5  + 2 * i];
                                  tb[i]     = (const float*)d_in[6  + 2 * i]; }
    for (int i = 0; i < 4; i++) { tw[4 + i] = (const float*)d_in[13 + 2 * i];
                                  tb[4 + i] = (const float*)d_in[14 + 2 * i]; }
    const float* csw = (const float*)d_in[21];
    const float* csb = (const float*)d_in[22];
    const float* bpw = (const float*)d_in[23];
    const float* bpb = (const float*)d_in[24];
    float* out = (float*)d_out;

    __nv_bfloat16 *X, *BA, *BB, *WT;
    cudaGetSymbolAddress((void**)&X,  g_X);
    cudaGetSymbolAddress((void**)&BA, g_bufA);
    cudaGetSymbolAddress((void**)&BB, g_bufB);
    cudaGetSymbolAddress((void**)&WT, g_wt);

    const size_t TS = (size_t)2304 * 256;
    __nv_bfloat16* wtC = WT + 8 * TS;
    __nv_bfloat16* wtB = wtC + (size_t)2304 * 768;

    // 1) all weight transforms, one launch (6782976 elems = 26496 blocks)
    Ptrs10 P;
    for (int i = 0; i < 8; i++) P.p[i] = tw[i];
    P.p[8] = csw; P.p[9] = bpw;
    wt_all<<<26496, 256>>>(P, WT);

    // 2) all level inputs -> unified NHWC bf16, one launch
    Ptrs5 F;
    for (int i = 0; i < 5; i++) F.p[i] = f[i];
    conv_in_all<<<NM, 256>>>(F, X);

    // 3) 4 fused tower layers (cls via z=0, box via z=1)
    __nv_bfloat16* bufs[2] = {BA, BB};
    GArgs a = {};
    const __nv_bfloat16* curC = X;
    const __nv_bfloat16* curB = X;
    for (int i = 0; i < 4; i++) {
        __nv_bfloat16* d = bufs[i & 1];
        a.srcA = curC;          a.srcB = curB;
        a.wA = WT + i * TS;     a.wB = WT + (4 + i) * TS;
        a.biasA = tb[i];        a.biasB = tb[4 + i];
        a.dstA = d;             a.dstB = d + HOFF;
        gemm_conv<0><<<dim3(MT, 2, 2), 256>>>(a);
        curC = d; curB = d + HOFF;
    }

    // 4) fused finals: y=0..5 cls (720 of 768), y=6 box (36 of 128)
    a.srcA = curC;  a.srcB = curB;
    a.wA = wtC;     a.wB = wtB;
    a.biasA = csb;  a.biasB = bpb;
    a.out = out;
    gemm_conv<1><<<dim3(MT, 7), 256>>>(a);
}

// round 17
// speedup vs baseline: 3.0282x; 1.0004x over previous
#include <cuda_runtime.h>
#include <cuda_bf16.h>
#include <cstdint>
#include <cstddef>

// ---------------------------------------------------------------------------
// RetinaNet head, all 5 FPN levels batched into ONE unified M dimension.
// Weights shared across levels => each conv layer = one implicit GEMM:
//   M = 2*(10000+2500+625+169+49) = 26686 rows (NHWC bf16), K = 9*256 = 2304.
// 7 launches total: wt_all, conv_in_all, 4x fused (cls+box) tower layers,
// 1 fused finals launch (6 cls n-tiles + 1 box n-tile) scattering straight
// into the permuted (N, 120087, 84) fp32 output.
// ---------------------------------------------------------------------------

#define DEVFN __device__ __forceinline__

constexpr int    RTOT = 120087;
constexpr int    NM   = 26686;              // total rows across levels & batch
constexpr int    MT   = (NM + 127) / 128;   // 209 M-tiles
constexpr size_t HOFF = (size_t)NM * 256;   // cls/box half offset in buffers

__constant__ int c_Moff[5] = {0, 20000, 25000, 26250, 26588};
__constant__ int c_HW[5]   = {10000, 2500, 625, 169, 49};
__constant__ int c_Wl[5]   = {100, 50, 25, 13, 7};
__constant__ int c_Roff[5] = {0, 90000, 112500, 118125, 119646};

DEVFN int level_of(int m) {
    return (m >= 20000) + (m >= 25000) + (m >= 26250) + (m >= 26588);
}

// ---------------- static device scratch (no allocations allowed) -----------
__device__ __align__(128) __nv_bfloat16 g_X   [(size_t)NM * 256];
__device__ __align__(128) __nv_bfloat16 g_bufA[2 * (size_t)NM * 256];
__device__ __align__(128) __nv_bfloat16 g_bufB[2 * (size_t)NM * 256];
// 8 tower convs (2304x256) + cls_score (2304x768 padded) + box_pred (2304x128)
__device__ __align__(128) __nv_bfloat16 g_wt[8 * 2304 * 256 + 2304 * 768 + 2304 * 128];

// ---------------- PTX helpers ----------------------------------------------
DEVFN uint32_t smem_u32(const void* p) {
    return (uint32_t)__cvta_generic_to_shared(p);
}
DEVFN void cp_async16(uint32_t dst, const void* src, int sz) {
    asm volatile("cp.async.cg.shared.global [%0], [%1], 16, %2;\n"
                 :: "r"(dst), "l"(src), "r"(sz));
}
DEVFN void cp_commit() { asm volatile("cp.async.commit_group;\n" ::: "memory"); }
template <int N> DEVFN void cp_wait() {
    asm volatile("cp.async.wait_group %0;\n" :: "n"(N) : "memory");
}
DEVFN void ldmat_x4(uint32_t* r, uint32_t addr) {
    asm volatile("ldmatrix.sync.aligned.m8n8.x4.shared.b16 {%0,%1,%2,%3}, [%4];\n"
                 : "=r"(r[0]), "=r"(r[1]), "=r"(r[2]), "=r"(r[3]) : "r"(addr));
}
DEVFN void ldmat_x4_t(uint32_t* r, uint32_t addr) {
    asm volatile("ldmatrix.sync.aligned.m8n8.x4.trans.shared.b16 {%0,%1,%2,%3}, [%4];\n"
                 : "=r"(r[0]), "=r"(r[1]), "=r"(r[2]), "=r"(r[3]) : "r"(addr));
}
DEVFN void mma16816(float* d, const uint32_t* a, const uint32_t* b) {
    asm volatile(
        "mma.sync.aligned.m16n8k16.row.col.f32.bf16.bf16.f32 "
        "{%0,%1,%2,%3},{%4,%5,%6,%7},{%8,%9},{%0,%1,%2,%3};\n"
        : "+f"(d[0]), "+f"(d[1]), "+f"(d[2]), "+f"(d[3])
        : "r"(a[0]), "r"(a[1]), "r"(a[2]), "r"(a[3]), "r"(b[0]), "r"(b[1]));
}

// ---------------- fused weight transform (one launch, all 10 convs) ---------
// (O,C,3,3) f32 -> [tap*256 + c][o] bf16, O padded to OP with zeros.
struct Ptrs10 { const float* p[10]; };

__global__ void wt_all(Ptrs10 Wsrc, __nv_bfloat16* __restrict__ dst) {
    int idx = blockIdx.x * 256 + threadIdx.x;
    const int TS    = 2304 * 256;
    const int C_END = 8 * TS + 2304 * 768;
    int which, base, OP, O;
    if (idx < 8 * TS)      { which = idx / TS; base = which * TS; OP = 256; O = 256; }
    else if (idx < C_END)  { which = 8; base = 8 * TS; OP = 768; O = 720; }
    else                   { which = 9; base = C_END;  OP = 128; O = 36; }
    int rel = idx - base;
    int row = rel / OP;
    int o   = rel - row * OP;
    int t = row >> 8, c = row & 255;
    float v = (o < O) ? Wsrc.p[which][((size_t)o * 256 + c) * 9 + t] : 0.f;
    dst[idx] = __float2bfloat16(v);
}

// ---------------- fused input convert: all levels NCHW f32 -> NHWC bf16 -----
struct Ptrs5 { const float* p[5]; };

__global__ void conv_in_all(Ptrs5 F, __nv_bfloat16* __restrict__ X) {
    int idx = blockIdx.x * 256 + threadIdx.x;   // exactly NM*256 threads
    int m = idx >> 8, c = idx & 255;
    int lvl = level_of(m);
    int rel = m - c_Moff[lvl];
    int HW  = c_HW[lvl];
    int n   = rel >= HW;
    int p   = rel - n * HW;
    X[idx] = __float2bfloat16(F.p[lvl][((size_t)n * 256 + c) * HW + p]);
}

// ---------------- the implicit-GEMM conv kernel -----------------------------
// BM=128 (unified spatial rows), BN=128, BK=32, 72 k-iters (9 taps x 8 chunks)
// 8 warps 2(M)x4(N), warp tile 64x32, mma m16n8k16, 3-stage cp.async.
// KIND 0: tower layer, blockIdx.z selects cls/box  (bias+relu -> bf16 NHWC)
// KIND 1: finals, blockIdx.y<6 = cls (OP=768, valid 720), ==6 = box (OP=128,
//         valid 36); scatter into out[(n*RTOT + Roff + p*9 + a)*84 + ...]
struct GArgs {
    const __nv_bfloat16* srcA;   // cls input
    const __nv_bfloat16* srcB;   // box input
    const __nv_bfloat16* wA;
    const __nv_bfloat16* wB;
    const float* biasA;
    const float* biasB;
    __nv_bfloat16* dstA;
    __nv_bfloat16* dstB;
    float* out;
};

template <int KIND>
__global__ __launch_bounds__(256, 2)
void gemm_conv(GArgs g) {
    __shared__ __align__(16) __nv_bfloat16 sA[3][128 * 32];
    __shared__ __align__(16) __nv_bfloat16 sB[3][32 * 128];

    const int tid  = threadIdx.x;
    const int lane = tid & 31, wid = tid >> 5;
    const int wm = wid & 1, wn = wid >> 1;
    const int mBase = blockIdx.x * 128;

    const __nv_bfloat16 *X, *Wt;
    const float* bias;
    __nv_bfloat16* Yb = nullptr;
    int OP, nBase, Ovalid = 0;
    bool clsmode = true;
    if (KIND == 0) {
        bool box = (blockIdx.z != 0);
        X    = box ? g.srcB  : g.srcA;
        Wt   = box ? g.wB    : g.wA;
        bias = box ? g.biasB : g.biasA;
        Yb   = box ? g.dstB  : g.dstA;
        OP = 256; nBase = blockIdx.y * 128;
    } else {
        clsmode = (blockIdx.y < 6);
        X    = clsmode ? g.srcA  : g.srcB;
        Wt   = clsmode ? g.wA    : g.wB;
        bias = clsmode ? g.biasA : g.biasB;
        OP     = clsmode ? 768 : 128;
        nBase  = clsmode ? (int)blockIdx.y * 128 : 0;
        Ovalid = clsmode ? 720 : 36;
    }

    // --- per-thread A-load bookkeeping: 2 rows x 1 chunk(16B), level decode ---
    const int ar = tid >> 2;   // 0..63
    const int ac = tid & 3;    // k-chunk within BK (8 bf16 each)
    int rowm[2], rx[2], ry[2], wd[2];
    bool rin[2];
#pragma unroll
    for (int i = 0; i < 2; i++) {
        int m = mBase + ar + i * 64;
        rowm[i] = m;
        bool inb = (m < NM);
        int mm = inb ? m : 0;
        int lvl = level_of(mm);
        int rel = mm - c_Moff[lvl];
        int HW  = c_HW[lvl];
        int Wd  = c_Wl[lvl];
        int n   = rel >= HW;
        int p   = rel - n * HW;
        ry[i] = p / Wd;
        rx[i] = p - ry[i] * Wd;
        wd[i] = Wd;
        rin[i] = inb;
    }
    // --- per-thread B-load bookkeeping: 1 row x 2 granules(16B) ---
    const int bk  = tid >> 3;  // 0..31
    const int bg0 = tid & 7;

    float acc[4][4][4];
#pragma unroll
    for (int a = 0; a < 4; a++)
#pragma unroll
        for (int b = 0; b < 4; b++)
#pragma unroll
            for (int c = 0; c < 4; c++) acc[a][b][c] = 0.f;

    auto load_tiles = [&](int kt, int st) {
        int tap = kt >> 3, cc = kt & 7;
        int dy = tap / 3 - 1, dx = (tap % 3) - 1;
        // A tile: conflict-free swizzle chunk' = ac ^ ((row>>1)&3)
#pragma unroll
        for (int i = 0; i < 2; i++) {
            int r = ar + i * 64;
            bool v = rin[i] && (unsigned)(ry[i] + dy) < (unsigned)wd[i] &&
                     (unsigned)(rx[i] + dx) < (unsigned)wd[i];
            size_t gidx = v ? ((size_t)(rowm[i] + dy * wd[i] + dx) * 256 + cc * 32 + ac * 8)
                            : (size_t)0;
            uint32_t dst = smem_u32(&sA[st][r * 32 + ((ac ^ ((r >> 1) & 3)) << 3)]);
            cp_async16(dst, X + gidx, v ? 16 : 0);
        }
        // B tile: 32 k-rows x 128 cols (granule g ^ (k & 7))
        const __nv_bfloat16* wrow = Wt + (size_t)(kt * 32 + bk) * OP + nBase;
#pragma unroll
        for (int i = 0; i < 2; i++) {
            int gg = bg0 + i * 8;
            uint32_t dst = smem_u32(&sB[st][bk * 128 + ((gg ^ (bk & 7)) << 3)]);
            cp_async16(dst, wrow + gg * 8, 16);
        }
        cp_commit();
    };

    load_tiles(0, 0);
    load_tiles(1, 1);

#pragma unroll 1
    for (int kt = 0; kt < 72; kt++) {
        int st = kt % 3;
        cp_wait<1>();
        __syncthreads();
        if (kt + 2 < 72) load_tiles(kt + 2, (kt + 2) % 3);
        else             cp_commit();   // keep group counting aligned

#pragma unroll
        for (int ks = 0; ks < 2; ks++) {
            uint32_t afr[4][4], bfr[2][4];
#pragma unroll
            for (int mi = 0; mi < 4; mi++) {
                int row = wm * 64 + mi * 16 + (lane & 15);
                int ch  = ks * 2 + (lane >> 4);
                ldmat_x4(afr[mi],
                         smem_u32(&sA[st][row * 32 + ((ch ^ ((row >> 1) & 3)) << 3)]));
            }
#pragma unroll
            for (int pr = 0; pr < 2; pr++) {
                int k = ks * 16 + ((lane >> 3) & 1) * 8 + (lane & 7);
                int gg = wn * 4 + pr * 2 + (lane >> 4);
                ldmat_x4_t(bfr[pr],
                           smem_u32(&sB[st][k * 128 + ((gg ^ (k & 7)) << 3)]));
            }
#pragma unroll
            for (int mi = 0; mi < 4; mi++)
#pragma unroll
                for (int ni = 0; ni < 4; ni++)
                    mma16816(acc[mi][ni], afr[mi], &bfr[ni >> 1][(ni & 1) * 2]);
        }
    }

    // ------------------------------ epilogue ------------------------------
    const int g4 = lane >> 2;  // accumulator row within 8
    const int q  = lane & 3;   // accumulator col pair
#pragma unroll
    for (int mi = 0; mi < 4; mi++) {
#pragma unroll
        for (int half = 0; half < 2; half++) {
            int m = mBase + wm * 64 + mi * 16 + g4 + half * 8;
            if (m >= NM) continue;
            if (KIND == 0) {
#pragma unroll
                for (int ni = 0; ni < 4; ni++) {
                    int col = nBase + wn * 32 + ni * 8 + q * 2;
                    float v0 = fmaxf(acc[mi][ni][half * 2 + 0] + bias[col], 0.f);
                    float v1 = fmaxf(acc[mi][ni][half * 2 + 1] + bias[col + 1], 0.f);
                    *reinterpret_cast<__nv_bfloat162*>(Yb + (size_t)m * 256 + col) =
                        __floats2bfloat162_rn(v0, v1);
                }
            } else {
                int lvl = level_of(m);
                int rel = m - c_Moff[lvl];
                int HW  = c_HW[lvl];
                int n   = rel >= HW;
                int p   = rel - n * HW;
                size_t rowbase = (size_t)n * RTOT + c_Roff[lvl] + (size_t)p * 9;
#pragma unroll
                for (int ni = 0; ni < 4; ni++) {
                    int col = nBase + wn * 32 + ni * 8 + q * 2;
#pragma unroll
                    for (int e = 0; e < 2; e++) {
                        int o = col + e;
                        if (o < Ovalid) {
                            float v = acc[mi][ni][half * 2 + e] + bias[o];
                            if (clsmode) {
                                int a = o / 80, kk = o - a * 80;
                                g.out[(rowbase + a) * 84 + kk] = v;
                            } else {
                                int a = o >> 2, j = o & 3;
                                g.out[(rowbase + a) * 84 + 80 + j] = v;
                            }
                        }
                    }
                }
            }
        }
    }
}

// ---------------- host launcher ---------------------------------------------
extern "C" void kernel_launch(void* const* d_in, const int* in_sizes, int n_in,
                              void* d_out, int out_size) {
    (void)in_sizes; (void)n_in; (void)out_size;

    const float* f[5];
    for (int i = 0; i < 5; i++) f[i] = (const float*)d_in[i];
    const float *tw[8], *tb[8];
    for (int i = 0; i < 4; i++) { tw[i]     = (const float*)d_in[5  + 2 * i];
                                  tb[i]     = (const float*)d_in[6  + 2 * i]; }
    for (int i = 0; i < 4; i++) { tw[4 + i] = (const float*)d_in[13 + 2 * i];
                                  tb[4 + i] = (const float*)d_in[14 + 2 * i]; }
    const float* csw = (const float*)d_in[21];
    const float* csb = (const float*)d_in[22];
    const float* bpw = (const float*)d_in[23];
    const float* bpb = (const float*)d_in[24];
    float* out = (float*)d_out;

    __nv_bfloat16 *X, *BA, *BB, *WT;
    cudaGetSymbolAddress((void**)&X,  g_X);
    cudaGetSymbolAddress((void**)&BA, g_bufA);
    cudaGetSymbolAddress((void**)&BB, g_bufB);
    cudaGetSymbolAddress((void**)&WT, g_wt);

    const size_t TS = (size_t)2304 * 256;
    __nv_bfloat16* wtC = WT + 8 * TS;
    __nv_bfloat16* wtB = wtC + (size_t)2304 * 768;

    // 1) all weight transforms, one launch (6782976 elems = 26496 blocks)
    Ptrs10 P;
    for (int i = 0; i < 8; i++) P.p[i] = tw[i];
    P.p[8] = csw; P.p[9] = bpw;
    wt_all<<<26496, 256>>>(P, WT);

    // 2) all level inputs -> unified NHWC bf16, one launch
    Ptrs5 F;
    for (int i = 0; i < 5; i++) F.p[i] = f[i];
    conv_in_all<<<NM, 256>>>(F, X);

    // 3) 4 fused tower layers (cls via z=0, box via z=1)
    __nv_bfloat16* bufs[2] = {BA, BB};
    GArgs a = {};
    const __nv_bfloat16* curC = X;
    const __nv_bfloat16* curB = X;
    for (int i = 0; i < 4; i++) {
        __nv_bfloat16* d = bufs[i & 1];
        a.srcA = curC;          a.srcB = curB;
        a.wA = WT + i * TS;     a.wB = WT + (4 + i) * TS;
        a.biasA = tb[i];        a.biasB = tb[4 + i];
        a.dstA = d;             a.dstB = d + HOFF;
        gemm_conv<0><<<dim3(MT, 2, 2), 256>>>(a);
        curC = d; curB = d + HOFF;
    }

    // 4) fused finals: y=0..5 cls (720 of 768), y=6 box (36 of 128)
    a.srcA = curC;  a.srcB = curB;
    a.wA = wtC;     a.wB = wtB;
    a.biasA = csb;  a.biasB = bpb;
    a.out = out;
    gemm_conv<1><<<dim3(MT, 7), 256>>>(a);
}